// round 14
// baseline (speedup 1.0000x reference)
#include <cuda_runtime.h>
#include <cuda_bf16.h>

// ---------------------------------------------------------------------------
// HardTripletMiningLoss  (n=3B=480, D=128)
//   gram = E E^T ;  pd[i,j] = max(sq_i + sq_j - 2 gram_ij, 0)
//   loss = mean over {i!=0, lab[i]==lab[j], lab[k]!=lab[j], td>0} of
//          td = pd[i,j] - pd[j,k] + A
// R14: gram inner loop uses PACKED fma.rn.f32x2 (sm_103a FFMA2; 1 instr =
//      2 MACs) with pre-duplicated A tile (float2{v,v}) and k-major B so all
//      operands are direct LDS.64 -> 8 instr per 8 MACs. Triplet -> 256 thr.
//      PDL chain kept from R12.
// ---------------------------------------------------------------------------

#define MAX_N    768
#define MAXW     ((MAX_N + 31) / 32)
#define POSCAP   128
#define MARGIN_A 0.2f
#define TR       32      // gram tile rows
#define TCN      64      // gram tile cols
#define KSPLIT   8
#define KC       16      // D / KSPLIT for D=128
#define TTH      256     // triplet threads
#define TNW      8       // triplet warps

static __device__ float g_part[KSPLIT][MAX_N * MAX_N];
static __device__ float g_sqp [KSPLIT][MAX_N];
static __device__ float g_ps[MAX_N];
static __device__ int   g_pc[MAX_N];

typedef unsigned long long u64;

__device__ __forceinline__ void pdl_wait() {
    asm volatile("griddepcontrol.wait;" ::: "memory");
}
__device__ __forceinline__ void pdl_launch_dependents() {
    asm volatile("griddepcontrol.launch_dependents;" ::: "memory");
}
__device__ __forceinline__ void fma2(u64& d, u64 a, u64 b) {
    asm("fma.rn.f32x2 %0, %1, %2, %0;" : "+l"(d) : "l"(a), "l"(b));
}

__device__ __forceinline__ const float* row_ptr(const float* a, const float* p,
                                                const float* ng, int r, int B, int D) {
    if (r < B)      return a  + (size_t)r * D;
    if (r < 2 * B)  return p  + (size_t)(r - B) * D;
    return ng + (size_t)(r - 2 * B) * D;
}

// ---------------------------------------------------------------------------
// gram: grid (ceil(n/64), ceil(n/32), KSPLIT), 256 thr, 2 rows x 4 cols each.
// Inner loop per k: 4 LDS.64 + 4 fma.rn.f32x2  (8 MACs).
// ---------------------------------------------------------------------------
__global__ void gram_kernel(const float* __restrict__ anchor,
                            const float* __restrict__ positive,
                            const float* __restrict__ negative,
                            int n, int B, int D) {
    __shared__ float2 As2[TR][KC];      // A duplicated: {v, v}  (4 KB)
    __shared__ float  BsT[KC][TCN];     // k-major transposed    (4 KB)

    const int bi  = blockIdx.y * TR;
    const int bj  = blockIdx.x * TCN;
    const int z   = blockIdx.z;
    const int k0  = z * KC;
    const int tid = threadIdx.x;        // 256 threads

    // load As duplicated: 32 rows x 4 float4 = 128 loads (tid < 128)
    if (tid < TR * 4) {
        const int r  = tid >> 2;
        const int c4 = tid & 3;
        const int gr = (bi + r < n) ? bi + r : n - 1;
        const float4 v = *(const float4*)(row_ptr(anchor, positive, negative, gr, B, D) + k0 + c4 * 4);
        const int k = c4 * 4;
        As2[r][k + 0] = make_float2(v.x, v.x);
        As2[r][k + 1] = make_float2(v.y, v.y);
        As2[r][k + 2] = make_float2(v.z, v.z);
        As2[r][k + 3] = make_float2(v.w, v.w);
    }
    // load BsT transposed: 64 cols x 4 float4 (one per thread)
    {
        const int col = tid & (TCN - 1);
        const int c4  = tid >> 6;        // 0..3
        const int gc  = (bj + col < n) ? bj + col : n - 1;
        const float4 v = *(const float4*)(row_ptr(anchor, positive, negative, gc, B, D) + k0 + c4 * 4);
        const int k = c4 * 4;
        BsT[k + 0][col] = v.x;
        BsT[k + 1][col] = v.y;
        BsT[k + 2][col] = v.z;
        BsT[k + 3][col] = v.w;
    }
    __syncthreads();

    const int tx = tid & 15;            // 16 col-groups x 4 cols
    const int ty = tid >> 4;            // 16 row-groups x 2 rows
    const int r0 = ty * 2;
    const int c0 = tx * 4;

    u64 acc0xy = 0ull, acc0zw = 0ull, acc1xy = 0ull, acc1zw = 0ull;

    #pragma unroll
    for (int k = 0; k < KC; k++) {
        const u64 x0  = *(const u64*)&As2[r0][k];          // {a0, a0}
        const u64 x1  = *(const u64*)&As2[r0 + 1][k];      // {a1, a1}
        const u64 bxy = *(const u64*)&BsT[k][c0];          // {b.x, b.y}
        const u64 bzw = *(const u64*)&BsT[k][c0 + 2];      // {b.z, b.w}
        fma2(acc0xy, x0, bxy);
        fma2(acc0zw, x0, bzw);
        fma2(acc1xy, x1, bxy);
        fma2(acc1zw, x1, bzw);
    }

    // unpack
    const float a0x = __uint_as_float((unsigned)acc0xy);
    const float a0y = __uint_as_float((unsigned)(acc0xy >> 32));
    const float a0z = __uint_as_float((unsigned)acc0zw);
    const float a0w = __uint_as_float((unsigned)(acc0zw >> 32));
    const float a1x = __uint_as_float((unsigned)acc1xy);
    const float a1y = __uint_as_float((unsigned)(acc1xy >> 32));
    const float a1z = __uint_as_float((unsigned)acc1zw);
    const float a1w = __uint_as_float((unsigned)(acc1zw >> 32));

    float* gp = g_part[z];
    const int gi0 = bi + r0;
    const int gj0 = bj + c0;
    if (gj0 < n) {                       // n%4==0 -> float4 in-bounds
        if (gi0 < n) {
            float4 v; v.x = a0x; v.y = a0y; v.z = a0z; v.w = a0w;
            *(float4*)&gp[(size_t)gi0 * n + gj0] = v;
            const int dq = gi0 - gj0;
            if (dq >= 0 && dq < 4) g_sqp[z][gi0] = (&v.x)[dq];
        }
        if (gi0 + 1 < n) {
            float4 v; v.x = a1x; v.y = a1y; v.z = a1z; v.w = a1w;
            *(float4*)&gp[(size_t)(gi0 + 1) * n + gj0] = v;
            const int dq = gi0 + 1 - gj0;
            if (dq >= 0 && dq < 4) g_sqp[z][gi0 + 1] = (&v.x)[dq];
        }
    }
    pdl_launch_dependents();
}

// ---------------------------------------------------------------------------
// Triplet: one block (256 thr) per j. Label work BEFORE pdl_wait (overlaps
// gram); gram-dependent work after. Branch-free fp32 hot loop (2 pdk slots).
// ---------------------------------------------------------------------------
__global__ void triplet_kernel(const int* __restrict__ ind, int n) {
    __shared__ float    pdrow[MAX_N];
    __shared__ int      labs[MAX_N];
    __shared__ short    slist[POSCAP];
    __shared__ float    avals[POSCAP];
    __shared__ unsigned chunkMask[MAXW];
    __shared__ int      chunkOff[MAXW];
    __shared__ int      nSame;
    __shared__ float    red_s[TNW];
    __shared__ int      red_c[TNW];

    const int j    = blockIdx.x;
    const int tid  = threadIdx.x;
    const int lane = tid & 31;
    const int wid  = tid >> 5;

    // ---------------- pre-wait: everything independent of gram --------------
    for (int t = tid; t < n; t += TTH)
        labs[t] = ind[t];
    __syncthreads();

    const int labj = labs[j];

    const int nChunks = (n + 31) >> 5;
    for (int c = wid; c < nChunks; c += TNW) {
        const int t = (c << 5) + lane;
        const bool pred = (t < n) && (t != 0) && (labs[t] == labj);
        const unsigned m = __ballot_sync(0xffffffffu, pred);
        if (lane == 0) chunkMask[c] = m;
    }
    __syncthreads();
    if (wid == 0) {                       // warp scan (nChunks <= 32)
        const unsigned m = (lane < nChunks) ? chunkMask[lane] : 0u;
        int p = __popc(m);
        #pragma unroll
        for (int o = 1; o < 32; o <<= 1) {
            const int t = __shfl_up_sync(0xffffffffu, p, o);
            if (lane >= o) p += t;
        }
        if (lane < nChunks) chunkOff[lane] = p - __popc(m);
        if (lane == 31) nSame = p;
    }
    __syncthreads();
    for (int c = wid; c < nChunks; c += TNW) {
        const unsigned m = chunkMask[c];
        const int t = (c << 5) + lane;
        if ((m >> lane) & 1u) {
            const int off = chunkOff[c] + __popc(m & ((1u << lane) - 1u));
            if (off < POSCAP) slist[off] = (short)t;
        }
    }
    __syncthreads();

    // ---------------- wait for gram, then consume its output ----------------
    pdl_wait();

    float sqj = g_sqp[0][j];
    #pragma unroll
    for (int z = 1; z < KSPLIT; z++) sqj += g_sqp[z][j];

    const size_t roff = (size_t)j * n;
    const int n4 = n >> 2;
    for (int v = tid; v < n4; v += TTH) {
        float4 g = ((const float4*)(g_part[0] + roff))[v];
        float4 q = ((const float4*)g_sqp[0])[v];
        #pragma unroll
        for (int z = 1; z < KSPLIT; z++) {
            const float4 gz = ((const float4*)(g_part[z] + roff))[v];
            const float4 qz = ((const float4*)g_sqp[z])[v];
            g.x += gz.x; g.y += gz.y; g.z += gz.z; g.w += gz.w;
            q.x += qz.x; q.y += qz.y; q.z += qz.z; q.w += qz.w;
        }
        float4 pd;
        pd.x = fmaxf(fmaf(-2.f, g.x, sqj + q.x), 0.f);
        pd.y = fmaxf(fmaf(-2.f, g.y, sqj + q.y), 0.f);
        pd.z = fmaxf(fmaf(-2.f, g.z, sqj + q.z), 0.f);
        pd.w = fmaxf(fmaf(-2.f, g.w, sqj + q.w), 0.f);
        ((float4*)pdrow)[v] = pd;
    }
    for (int v = (n4 << 2) + tid; v < n; v += TTH) {
        float g = 0.f, q = 0.f;
        #pragma unroll
        for (int z = 0; z < KSPLIT; z++) { g += g_part[z][roff + v]; q += g_sqp[z][v]; }
        pdrow[v] = fmaxf(fmaf(-2.f, g, sqj + q), 0.f);
    }
    __syncthreads();

    const int ns = (nSame < POSCAP) ? nSame : POSCAP;
    if (tid < ns)
        avals[tid] = pdrow[(int)slist[tid]] + MARGIN_A;

    float pdk0 = 3.4e38f, pdk1 = 3.4e38f;    // sentinels: never counted
    if (tid < n       && labs[tid]       != labj) pdk0 = pdrow[tid];
    if (tid + TTH < n && labs[tid + TTH] != labj) pdk1 = pdrow[tid + TTH];
    __syncthreads();

    float s = 0.f;
    int   c = 0;
    for (int q = 0; q < ns; q++) {
        const float aq = avals[q];
        const float v0 = aq - pdk0;
        const float v1 = aq - pdk1;
        if (v0 > 0.f) { s += v0; c++; }
        if (v1 > 0.f) { s += v1; c++; }
    }

    #pragma unroll
    for (int o = 16; o > 0; o >>= 1) {
        s += __shfl_down_sync(0xffffffffu, s, o);
        c += __shfl_down_sync(0xffffffffu, c, o);
    }
    if (lane == 0) { red_s[wid] = s; red_c[wid] = c; }
    __syncthreads();
    if (tid == 0) {
        float st = 0.f; int ct = 0;
        #pragma unroll
        for (int w = 0; w < TNW; w++) { st += red_s[w]; ct += red_c[w]; }
        g_ps[j] = st;
        g_pc[j] = ct;
    }
    pdl_launch_dependents();
}

// ---------------------------------------------------------------------------
// Final: single block, fp64 reduce of n partials (waits on triplet via PDL).
// ---------------------------------------------------------------------------
__global__ void final_kernel(float* __restrict__ out, int n) {
    __shared__ double red_s[4];
    __shared__ double red_c[4];
    const int tid  = threadIdx.x;
    const int lane = tid & 31;
    const int wid  = tid >> 5;

    pdl_wait();

    double s = 0.0, c = 0.0;
    for (int t = tid; t < n; t += 128) { s += (double)g_ps[t]; c += (double)g_pc[t]; }
    #pragma unroll
    for (int o = 16; o > 0; o >>= 1) {
        s += __shfl_down_sync(0xffffffffu, s, o);
        c += __shfl_down_sync(0xffffffffu, c, o);
    }
    if (lane == 0) { red_s[wid] = s; red_c[wid] = c; }
    __syncthreads();
    if (tid == 0) {
        double st = 0.0, ct = 0.0;
        #pragma unroll
        for (int w = 0; w < 4; w++) { st += red_s[w]; ct += red_c[w]; }
        out[0] = (ct > 0.0) ? (float)(st / (ct < 1.0 ? 1.0 : ct)) : 0.0f;
    }
}

extern "C" void kernel_launch(void* const* d_in, const int* in_sizes, int n_in,
                              void* d_out, int out_size) {
    const float* anchor   = (const float*)d_in[0];
    const float* positive = (const float*)d_in[1];
    const float* negative = (const float*)d_in[2];
    const int*   ind      = (const int*)d_in[3];

    const int n = in_sizes[3];          // 3B
    const int B = n / 3;
    const int D = in_sizes[0] / B;      // 128

    dim3 ggrid((n + TCN - 1) / TCN, (n + TR - 1) / TR, KSPLIT);  // 8x15x8
    gram_kernel<<<ggrid, 256>>>(anchor, positive, negative, n, B, D);

    cudaLaunchAttribute attr[1];
    attr[0].id = cudaLaunchAttributeProgrammaticStreamSerialization;
    attr[0].val.programmaticStreamSerializationAllowed = 1;

    cudaLaunchConfig_t cfg = {};
    cfg.attrs = attr;
    cfg.numAttrs = 1;
    cfg.stream = 0;

    cfg.gridDim  = dim3((unsigned)n, 1, 1);
    cfg.blockDim = dim3(TTH, 1, 1);
    cudaLaunchKernelEx(&cfg, triplet_kernel, ind, n);

    cfg.gridDim  = dim3(1, 1, 1);
    cfg.blockDim = dim3(128, 1, 1);
    cudaLaunchKernelEx(&cfg, final_kernel, (float*)d_out, n);
}

// round 15
// speedup vs baseline: 1.1215x; 1.1215x over previous
#include <cuda_runtime.h>
#include <cuda_bf16.h>
#include <stdint.h>

// ---------------------------------------------------------------------------
// HardTripletMiningLoss  (n=3B=480, D=128)
//   gram = E E^T ;  pd[i,j] = max(sq_i + sq_j - 2 gram_ij, 0)
//   loss = mean over {i!=0, lab[i]==lab[j], lab[k]!=lab[j], td>0} of
//          td = pd[i,j] - pd[j,k] + A
// R15: gram on TENSOR CORES: mma.sync.m16n8k8.tf32 with 3xTF32 split
//      (fp32-quality). 64x64 tile/block, 256 thr, K chunked 2x64, grid 8x8.
//      No KSPLIT -> triplet reconstruct reads ONE matrix. PDL chain kept.
// ---------------------------------------------------------------------------

#define MAX_N    768
#define MAXW     ((MAX_N + 31) / 32)
#define POSCAP   128
#define MARGIN_A 0.2f
#define GT       64      // gram tile (rows == cols)
#define KCH      64      // K chunk
#define SSTR     68      // smem row stride (== 4 mod 32 -> conflict-free frags)
#define TTH      256     // triplet threads
#define TNW      8

static __device__ float g_gram[MAX_N * MAX_N];
static __device__ float g_sq[MAX_N];
static __device__ float g_ps[MAX_N];
static __device__ int   g_pc[MAX_N];

__device__ __forceinline__ void pdl_wait() {
    asm volatile("griddepcontrol.wait;" ::: "memory");
}
__device__ __forceinline__ void pdl_launch_dependents() {
    asm volatile("griddepcontrol.launch_dependents;" ::: "memory");
}
__device__ __forceinline__ uint32_t tf32_hi(float x) {
    uint32_t h;
    asm("cvt.rna.tf32.f32 %0, %1;" : "=r"(h) : "f"(x));
    return h;
}
__device__ __forceinline__ void tf32_split(float x, uint32_t& hi, uint32_t& lo) {
    hi = tf32_hi(x);
    lo = tf32_hi(x - __uint_as_float(hi));
}
__device__ __forceinline__ void mma_tf32(float c[4],
                                         uint32_t a0, uint32_t a1, uint32_t a2, uint32_t a3,
                                         uint32_t b0, uint32_t b1) {
    asm volatile(
        "mma.sync.aligned.m16n8k8.row.col.f32.tf32.tf32.f32 "
        "{%0,%1,%2,%3},{%4,%5,%6,%7},{%8,%9},{%0,%1,%2,%3};"
        : "+f"(c[0]), "+f"(c[1]), "+f"(c[2]), "+f"(c[3])
        : "r"(a0), "r"(a1), "r"(a2), "r"(a3), "r"(b0), "r"(b1));
}

__device__ __forceinline__ const float* row_ptr(const float* a, const float* p,
                                                const float* ng, int r, int B, int D) {
    if (r < B)      return a  + (size_t)r * D;
    if (r < 2 * B)  return p  + (size_t)(r - B) * D;
    return ng + (size_t)(r - 2 * B) * D;
}

// ---------------------------------------------------------------------------
// gram (tensor): grid (ceil(n/64), ceil(n/64)), 256 thr.
// Warp (wr, wc) in 2x4 owns a 32x16 region = 2 row-tiles x 2 col-tiles of
// m16n8. Fragments loaded scalar from stride-68 smem (perfect bank perm).
// ---------------------------------------------------------------------------
__global__ void gram_kernel(const float* __restrict__ anchor,
                            const float* __restrict__ positive,
                            const float* __restrict__ negative,
                            int n, int B, int D) {
    extern __shared__ float smem[];
    float* sAh = smem;                       // [GT][SSTR]
    float* sAl = sAh + GT * SSTR;
    float* sBh = sAl + GT * SSTR;
    float* sBl = sBh + GT * SSTR;

    const int bi   = blockIdx.y * GT;
    const int bj   = blockIdx.x * GT;
    const int tid  = threadIdx.x;
    const int lane = tid & 31;
    const int wid  = tid >> 5;
    const int wr   = wid >> 2;               // 0..1
    const int wc   = wid & 3;                // 0..3
    const int g    = lane >> 2;              // 0..7
    const int tg   = lane & 3;               // 0..3

    float acc[2][2][4];
    #pragma unroll
    for (int rt = 0; rt < 2; rt++)
        #pragma unroll
        for (int ct = 0; ct < 2; ct++)
            #pragma unroll
            for (int q = 0; q < 4; q++) acc[rt][ct][q] = 0.f;

    const int nch = (D + KCH - 1) / KCH;
    for (int ch = 0; ch < nch; ch++) {
        const int k0 = ch * KCH;

        // ---- stage: A rows (bi..), B rows (bj..), split to tf32 hi/lo ----
        #pragma unroll
        for (int t = 0; t < 4; t++) {
            const int idx = tid + t * 256;   // 0..1023
            const int r   = idx >> 4;        // 0..63
            const int kk  = (idx & 15) * 4;  // 0..60
            const int gr  = (bi + r < n) ? bi + r : n - 1;
            const int gc  = (bj + r < n) ? bj + r : n - 1;
            float4 va, vb;
            if (k0 + kk + 4 <= D) {
                va = *(const float4*)(row_ptr(anchor, positive, negative, gr, B, D) + k0 + kk);
                vb = *(const float4*)(row_ptr(anchor, positive, negative, gc, B, D) + k0 + kk);
            } else {
                const float* ra = row_ptr(anchor, positive, negative, gr, B, D);
                const float* rb = row_ptr(anchor, positive, negative, gc, B, D);
                float ta[4], tb[4];
                #pragma unroll
                for (int e = 0; e < 4; e++) {
                    ta[e] = (k0 + kk + e < D) ? ra[k0 + kk + e] : 0.f;
                    tb[e] = (k0 + kk + e < D) ? rb[k0 + kk + e] : 0.f;
                }
                va.x = ta[0]; va.y = ta[1]; va.z = ta[2]; va.w = ta[3];
                vb.x = tb[0]; vb.y = tb[1]; vb.z = tb[2]; vb.w = tb[3];
            }
            uint32_t h0, l0, h1, l1, h2, l2, h3, l3;
            tf32_split(va.x, h0, l0); tf32_split(va.y, h1, l1);
            tf32_split(va.z, h2, l2); tf32_split(va.w, h3, l3);
            float4 hv, lv;
            hv.x = __uint_as_float(h0); hv.y = __uint_as_float(h1);
            hv.z = __uint_as_float(h2); hv.w = __uint_as_float(h3);
            lv.x = __uint_as_float(l0); lv.y = __uint_as_float(l1);
            lv.z = __uint_as_float(l2); lv.w = __uint_as_float(l3);
            *(float4*)&sAh[r * SSTR + kk] = hv;
            *(float4*)&sAl[r * SSTR + kk] = lv;
            tf32_split(vb.x, h0, l0); tf32_split(vb.y, h1, l1);
            tf32_split(vb.z, h2, l2); tf32_split(vb.w, h3, l3);
            hv.x = __uint_as_float(h0); hv.y = __uint_as_float(h1);
            hv.z = __uint_as_float(h2); hv.w = __uint_as_float(h3);
            lv.x = __uint_as_float(l0); lv.y = __uint_as_float(l1);
            lv.z = __uint_as_float(l2); lv.w = __uint_as_float(l3);
            *(float4*)&sBh[r * SSTR + kk] = hv;
            *(float4*)&sBl[r * SSTR + kk] = lv;
        }
        __syncthreads();

        // ---- mainloop: 8 k-steps of 8 ----
        #pragma unroll
        for (int s = 0; s < KCH / 8; s++) {
            const int ka = s * 8 + tg;
            uint32_t ah[2][4], al[2][4];
            #pragma unroll
            for (int rt = 0; rt < 2; rt++) {
                const int r0 = (wr * 32 + rt * 16 + g) * SSTR;
                const int r1 = r0 + 8 * SSTR;
                ah[rt][0] = __float_as_uint(sAh[r0 + ka]);
                ah[rt][1] = __float_as_uint(sAh[r1 + ka]);
                ah[rt][2] = __float_as_uint(sAh[r0 + ka + 4]);
                ah[rt][3] = __float_as_uint(sAh[r1 + ka + 4]);
                al[rt][0] = __float_as_uint(sAl[r0 + ka]);
                al[rt][1] = __float_as_uint(sAl[r1 + ka]);
                al[rt][2] = __float_as_uint(sAl[r0 + ka + 4]);
                al[rt][3] = __float_as_uint(sAl[r1 + ka + 4]);
            }
            uint32_t bh[2][2], bl[2][2];
            #pragma unroll
            for (int ct = 0; ct < 2; ct++) {
                const int cb = (wc * 16 + ct * 8 + g) * SSTR;
                bh[ct][0] = __float_as_uint(sBh[cb + ka]);
                bh[ct][1] = __float_as_uint(sBh[cb + ka + 4]);
                bl[ct][0] = __float_as_uint(sBl[cb + ka]);
                bl[ct][1] = __float_as_uint(sBl[cb + ka + 4]);
            }
            #pragma unroll
            for (int rt = 0; rt < 2; rt++)
                #pragma unroll
                for (int ct = 0; ct < 2; ct++) {
                    mma_tf32(acc[rt][ct], al[rt][0], al[rt][1], al[rt][2], al[rt][3],
                             bh[ct][0], bh[ct][1]);
                    mma_tf32(acc[rt][ct], ah[rt][0], ah[rt][1], ah[rt][2], ah[rt][3],
                             bl[ct][0], bl[ct][1]);
                    mma_tf32(acc[rt][ct], ah[rt][0], ah[rt][1], ah[rt][2], ah[rt][3],
                             bh[ct][0], bh[ct][1]);
                }
        }
        __syncthreads();
    }

    // ---- epilogue: float2 stores + diagonal extraction ----
    #pragma unroll
    for (int rt = 0; rt < 2; rt++) {
        #pragma unroll
        for (int ct = 0; ct < 2; ct++) {
            const int gi0 = bi + wr * 32 + rt * 16 + g;
            const int gi1 = gi0 + 8;
            const int gj  = bj + wc * 16 + ct * 8 + 2 * tg;
            const float* c = acc[rt][ct];
            if (gj < n) {
                if (gi0 < n) {
                    *(float2*)&g_gram[(size_t)gi0 * n + gj] = make_float2(c[0], c[1]);
                    if      (gj     == gi0) g_sq[gi0] = c[0];
                    else if (gj + 1 == gi0) g_sq[gi0] = c[1];
                }
                if (gi1 < n) {
                    *(float2*)&g_gram[(size_t)gi1 * n + gj] = make_float2(c[2], c[3]);
                    if      (gj     == gi1) g_sq[gi1] = c[2];
                    else if (gj + 1 == gi1) g_sq[gi1] = c[3];
                }
            }
        }
    }
    pdl_launch_dependents();
}

// ---------------------------------------------------------------------------
// Triplet: one block (256 thr) per j. Label work BEFORE pdl_wait (overlaps
// gram); single-matrix reconstruct after. Branch-free fp32 hot loop.
// ---------------------------------------------------------------------------
__global__ void triplet_kernel(const int* __restrict__ ind, int n) {
    __shared__ float    pdrow[MAX_N];
    __shared__ int      labs[MAX_N];
    __shared__ short    slist[POSCAP];
    __shared__ float    avals[POSCAP];
    __shared__ unsigned chunkMask[MAXW];
    __shared__ int      chunkOff[MAXW];
    __shared__ int      nSame;
    __shared__ float    red_s[TNW];
    __shared__ int      red_c[TNW];

    const int j    = blockIdx.x;
    const int tid  = threadIdx.x;
    const int lane = tid & 31;
    const int wid  = tid >> 5;

    // ---------------- pre-wait: everything independent of gram --------------
    for (int t = tid; t < n; t += TTH)
        labs[t] = ind[t];
    __syncthreads();

    const int labj = labs[j];

    const int nChunks = (n + 31) >> 5;
    for (int c = wid; c < nChunks; c += TNW) {
        const int t = (c << 5) + lane;
        const bool pred = (t < n) && (t != 0) && (labs[t] == labj);
        const unsigned m = __ballot_sync(0xffffffffu, pred);
        if (lane == 0) chunkMask[c] = m;
    }
    __syncthreads();
    if (wid == 0) {                       // warp scan (nChunks <= 32)
        const unsigned m = (lane < nChunks) ? chunkMask[lane] : 0u;
        int p = __popc(m);
        #pragma unroll
        for (int o = 1; o < 32; o <<= 1) {
            const int t = __shfl_up_sync(0xffffffffu, p, o);
            if (lane >= o) p += t;
        }
        if (lane < nChunks) chunkOff[lane] = p - __popc(m);
        if (lane == 31) nSame = p;
    }
    __syncthreads();
    for (int c = wid; c < nChunks; c += TNW) {
        const unsigned m = chunkMask[c];
        const int t = (c << 5) + lane;
        if ((m >> lane) & 1u) {
            const int off = chunkOff[c] + __popc(m & ((1u << lane) - 1u));
            if (off < POSCAP) slist[off] = (short)t;
        }
    }
    __syncthreads();

    // ---------------- wait for gram, then consume its output ----------------
    pdl_wait();

    const float sqj = g_sq[j];
    const float* rowp = g_gram + (size_t)j * n;
    const int n4 = n >> 2;
    for (int v = tid; v < n4; v += TTH) {
        const float4 gv = ((const float4*)rowp)[v];
        const float4 qv = ((const float4*)g_sq)[v];
        float4 pd;
        pd.x = fmaxf(fmaf(-2.f, gv.x, sqj + qv.x), 0.f);
        pd.y = fmaxf(fmaf(-2.f, gv.y, sqj + qv.y), 0.f);
        pd.z = fmaxf(fmaf(-2.f, gv.z, sqj + qv.z), 0.f);
        pd.w = fmaxf(fmaf(-2.f, gv.w, sqj + qv.w), 0.f);
        ((float4*)pdrow)[v] = pd;
    }
    for (int v = (n4 << 2) + tid; v < n; v += TTH)
        pdrow[v] = fmaxf(fmaf(-2.f, rowp[v], sqj + g_sq[v]), 0.f);
    __syncthreads();

    const int ns = (nSame < POSCAP) ? nSame : POSCAP;
    if (tid < ns)
        avals[tid] = pdrow[(int)slist[tid]] + MARGIN_A;

    float pdk0 = 3.4e38f, pdk1 = 3.4e38f;    // sentinels: never counted
    if (tid < n       && labs[tid]       != labj) pdk0 = pdrow[tid];
    if (tid + TTH < n && labs[tid + TTH] != labj) pdk1 = pdrow[tid + TTH];
    __syncthreads();

    float s = 0.f;
    int   c = 0;
    for (int q = 0; q < ns; q++) {
        const float aq = avals[q];
        const float v0 = aq - pdk0;
        const float v1 = aq - pdk1;
        if (v0 > 0.f) { s += v0; c++; }
        if (v1 > 0.f) { s += v1; c++; }
    }

    #pragma unroll
    for (int o = 16; o > 0; o >>= 1) {
        s += __shfl_down_sync(0xffffffffu, s, o);
        c += __shfl_down_sync(0xffffffffu, c, o);
    }
    if (lane == 0) { red_s[wid] = s; red_c[wid] = c; }
    __syncthreads();
    if (tid == 0) {
        float st = 0.f; int ct = 0;
        #pragma unroll
        for (int w = 0; w < TNW; w++) { st += red_s[w]; ct += red_c[w]; }
        g_ps[j] = st;
        g_pc[j] = ct;
    }
    pdl_launch_dependents();
}

// ---------------------------------------------------------------------------
// Final: single block, fp64 reduce of n partials (waits on triplet via PDL).
// ---------------------------------------------------------------------------
__global__ void final_kernel(float* __restrict__ out, int n) {
    __shared__ double red_s[4];
    __shared__ double red_c[4];
    const int tid  = threadIdx.x;
    const int lane = tid & 31;
    const int wid  = tid >> 5;

    pdl_wait();

    double s = 0.0, c = 0.0;
    for (int t = tid; t < n; t += 128) { s += (double)g_ps[t]; c += (double)g_pc[t]; }
    #pragma unroll
    for (int o = 16; o > 0; o >>= 1) {
        s += __shfl_down_sync(0xffffffffu, s, o);
        c += __shfl_down_sync(0xffffffffu, c, o);
    }
    if (lane == 0) { red_s[wid] = s; red_c[wid] = c; }
    __syncthreads();
    if (tid == 0) {
        double st = 0.0, ct = 0.0;
        #pragma unroll
        for (int w = 0; w < 4; w++) { st += red_s[w]; ct += red_c[w]; }
        out[0] = (ct > 0.0) ? (float)(st / (ct < 1.0 ? 1.0 : ct)) : 0.0f;
    }
}

extern "C" void kernel_launch(void* const* d_in, const int* in_sizes, int n_in,
                              void* d_out, int out_size) {
    const float* anchor   = (const float*)d_in[0];
    const float* positive = (const float*)d_in[1];
    const float* negative = (const float*)d_in[2];
    const int*   ind      = (const int*)d_in[3];

    const int n = in_sizes[3];          // 3B
    const int B = n / 3;
    const int D = in_sizes[0] / B;      // 128

    const int smemBytes = 4 * GT * SSTR * (int)sizeof(float);   // ~69.6 KB
    cudaFuncSetAttribute(gram_kernel,
                         cudaFuncAttributeMaxDynamicSharedMemorySize, smemBytes);

    dim3 ggrid((n + GT - 1) / GT, (n + GT - 1) / GT);           // 8x8
    gram_kernel<<<ggrid, 256, smemBytes>>>(anchor, positive, negative, n, B, D);

    cudaLaunchAttribute attr[1];
    attr[0].id = cudaLaunchAttributeProgrammaticStreamSerialization;
    attr[0].val.programmaticStreamSerializationAllowed = 1;

    cudaLaunchConfig_t cfg = {};
    cfg.attrs = attr;
    cfg.numAttrs = 1;
    cfg.stream = 0;

    cfg.gridDim  = dim3((unsigned)n, 1, 1);
    cfg.blockDim = dim3(TTH, 1, 1);
    cudaLaunchKernelEx(&cfg, triplet_kernel, ind, n);

    cfg.gridDim  = dim3(1, 1, 1);
    cfg.blockDim = dim3(128, 1, 1);
    cudaLaunchKernelEx(&cfg, final_kernel, (float*)d_out, n);
}